// round 16
// baseline (speedup 1.0000x reference)
#include <cuda_runtime.h>
#include <cuda_fp16.h>
#include <stdint.h>
#include <math.h>
#include <float.h>

#define B_ROWS 16384
#define NCLS   1000
#define KDIM   1000
#define EPS    0.1f

// GEMM config: centered fp16 single-term, K = 1024
#define KPA     1024
#define BM      128
#define BN      128
#define BK      64            // fp16 K per stage = 128 bytes/row
#define KITERS  (KPA / BK)    // 16
#define NSTAGE  3
#define STAGE_BYTES 32768     // A 16KB + B 16KB
#define SMEM_TOTAL (NSTAGE * STAGE_BYTES)   // 96 KB
#define NTILES  16            // 16 x 64-col softmax partial tiles
#define NBLK    (B_ROWS / 256)              // 64 combine blocks

// Scratch (__device__ globals: allocation-free rule)
__device__ float4   g_part[NTILES][B_ROWS];   // {max, sumexp, sum, S[label]}
__device__ float    g_bsum[NBLK];
__device__ int      g_labmode;
__device__ unsigned g_done;                   // combine last-block counter (self-resetting)
__device__ __half   g_Ah[(size_t)B_ROWS * KPA];  // fp16(a - 0.5)
__device__ __half   g_Ch[(size_t)1024  * KPA];   // fp16(c - 0.5), rows padded

// ---------------------------------------------------------------- PTX helpers
__device__ __forceinline__ uint32_t smem_u32(const void* p) {
    uint32_t a;
    asm("{ .reg .u64 t; cvta.to.shared.u64 t, %1; cvt.u32.u64 %0, t; }" : "=r"(a) : "l"(p));
    return a;
}
#define CP_ASYNC16(dst, src) \
    asm volatile("cp.async.cg.shared.global [%0], [%1], 16;\n" :: "r"(dst), "l"(src))
#define CP_COMMIT() asm volatile("cp.async.commit_group;\n" ::: "memory")
#define CP_WAIT1()  asm volatile("cp.async.wait_group 1;\n" ::: "memory")

__device__ __forceinline__ void ldmx4(uint32_t& r0, uint32_t& r1, uint32_t& r2,
                                      uint32_t& r3, uint32_t addr) {
    asm volatile("ldmatrix.sync.aligned.m8n8.x4.shared.b16 {%0,%1,%2,%3}, [%4];"
                 : "=r"(r0), "=r"(r1), "=r"(r2), "=r"(r3) : "r"(addr));
}
__device__ __forceinline__ void mma_fp16(float* c, const uint32_t* a, const uint32_t* b) {
    asm volatile("mma.sync.aligned.m16n8k16.row.col.f32.f16.f16.f32 "
                 "{%0,%1,%2,%3}, {%4,%5,%6,%7}, {%8,%9}, {%0,%1,%2,%3};"
                 : "+f"(c[0]), "+f"(c[1]), "+f"(c[2]), "+f"(c[3])
                 : "r"(a[0]), "r"(a[1]), "r"(a[2]), "r"(a[3]), "r"(b[0]), "r"(b[1]));
}

// ------------------------------------------------ fused prep (conv + detect)
// 16 elements per thread (4 independent float4 loads -> MLP 4).
// blocks [0, 4096)      : convert A
// blocks [4096, 4352)   : convert C
// block  4352           : label-dtype detect + g_done reset
#define A_BLKS 4096
#define C_BLKS 256
__device__ __forceinline__ void conv16(const float* __restrict__ src, bool rok,
                                       int k, __half* __restrict__ dst) {
    float v[16];
    if (rok && k + 16 <= KDIM) {
        float4 x0 = *(const float4*)(src + k);
        float4 x1 = *(const float4*)(src + k + 4);
        float4 x2 = *(const float4*)(src + k + 8);
        float4 x3 = *(const float4*)(src + k + 12);
        v[0]=x0.x-0.5f;  v[1]=x0.y-0.5f;  v[2]=x0.z-0.5f;  v[3]=x0.w-0.5f;
        v[4]=x1.x-0.5f;  v[5]=x1.y-0.5f;  v[6]=x1.z-0.5f;  v[7]=x1.w-0.5f;
        v[8]=x2.x-0.5f;  v[9]=x2.y-0.5f;  v[10]=x2.z-0.5f; v[11]=x2.w-0.5f;
        v[12]=x3.x-0.5f; v[13]=x3.y-0.5f; v[14]=x3.z-0.5f; v[15]=x3.w-0.5f;
    } else {
        #pragma unroll
        for (int i = 0; i < 16; i++) {
            int kk = k + i;
            v[i] = (rok && kk < KDIM) ? (src[kk] - 0.5f) : 0.f;
        }
    }
    union { __half h[16]; uint4 q[2]; } u;
    #pragma unroll
    for (int i = 0; i < 16; i++) u.h[i] = __float2half_rn(v[i]);
    *(uint4*)(dst)     = u.q[0];
    *(uint4*)(dst + 8) = u.q[1];
}

__global__ void prep_kernel(const float* __restrict__ A,
                            const float* __restrict__ Cb,
                            const int* __restrict__ l32) {
    const int bid = blockIdx.x;
    if (bid < A_BLKS) {
        size_t t = (size_t)bid * 256 + threadIdx.x;
        int b = (int)(t >> 6);
        int k = (int)(t & 63) << 4;
        conv16(A + (size_t)b * KDIM, true, k, g_Ah + (size_t)b * KPA + k);
    } else if (bid < A_BLKS + C_BLKS) {
        size_t t = (size_t)(bid - A_BLKS) * 256 + threadIdx.x;
        int n = (int)(t >> 6);
        int k = (int)(t & 63) << 4;
        conv16(Cb + (size_t)n * KDIM, n < NCLS, k, g_Ch + (size_t)n * KPA + k);
    } else {
        __shared__ int s_any;
        if (threadIdx.x == 0) { s_any = 0; g_done = 0; }
        __syncthreads();
        int local = 0;
        for (int i = threadIdx.x; i < B_ROWS / 2; i += blockDim.x)
            local |= l32[2 * i + 1];
        if (local) atomicOr(&s_any, 1);
        __syncthreads();
        if (threadIdx.x == 0) g_labmode = (s_any != 0) ? 1 : 0;
    }
}

// ---------------------------------------------------------------- HMMA GEMM
// 8 warps x (32x64) warp tiles on 128x128 CTA tile (R13-proven config).
// Computes S = 2 * (A' @ C'^T) and fused softmax partials per 64-col tile.
__global__ void __launch_bounds__(256, 2)
gemm_kernel(const int* __restrict__ l32) {
    extern __shared__ char smem[];
    const uint32_t sb = smem_u32(smem);

    const int tid  = threadIdx.x;
    const int lane = tid & 31;
    const int wid  = tid >> 5;
    const int wm   = wid >> 1;        // 0..3  -> m offset wm*32
    const int wn   = wid & 1;         // 0..1  -> n offset wn*64
    const int m0   = blockIdx.y * BM;
    const int n0   = blockIdx.x * BN;

    // cp.async staging mapping: each thread owns 4 A-chunks + 4 B-chunks/stage
    const int srow = tid >> 3;        // 0..31 base row
    const int scol = tid & 7;         // chunk 0..7
    const uint32_t sdst = srow * 128 + ((scol ^ (srow & 7)) * 16);
    const __half* Asrc = g_Ah + (size_t)(m0 + srow) * KPA + scol * 8;
    const __half* Bsrc = g_Ch + (size_t)(n0 + srow) * KPA + scol * 8;

    auto load_stage = [&](int s, int st) {
        const int k0 = s * BK;
        const uint32_t sA = sb + st * STAGE_BYTES;
        const uint32_t sB = sA + 16384;
        #pragma unroll
        for (int i = 0; i < 4; i++) {
            uint32_t d = sA + sdst + i * 32 * 128;
            CP_ASYNC16(d, Asrc + (size_t)(32 * i) * KPA + k0);
        }
        #pragma unroll
        for (int i = 0; i < 4; i++) {
            uint32_t d = sB + sdst + i * 32 * 128;
            CP_ASYNC16(d, Bsrc + (size_t)(32 * i) * KPA + k0);
        }
        CP_COMMIT();
    };

    float acc[2][8][4];
    #pragma unroll
    for (int mi = 0; mi < 2; mi++)
        #pragma unroll
        for (int ni = 0; ni < 8; ni++)
            #pragma unroll
            for (int j = 0; j < 4; j++) acc[mi][ni][j] = 0.f;

    const int a_row = wm * 32 + (lane & 15);
    const int a_hi  = lane >> 4;
    const int b_row = wn * 64 + (lane & 7) + ((lane >> 4) << 3);
    const int b_hi  = (lane >> 3) & 1;

    load_stage(0, 0);
    load_stage(1, 1);

    for (int s = 0; s < KITERS; s++) {
        const int st = s % NSTAGE;
        CP_WAIT1();
        __syncthreads();
        if (s + 2 < KITERS) load_stage(s + 2, (s + 2) % NSTAGE);

        const uint32_t sA = sb + st * STAGE_BYTES;
        const uint32_t sB = sA + 16384;

        #pragma unroll
        for (int kk = 0; kk < 4; kk++) {
            uint32_t af[2][4];
            #pragma unroll
            for (int mi = 0; mi < 2; mi++) {
                int row = a_row + mi * 16;
                uint32_t addr = sA + row * 128
                              + (((kk * 2 + a_hi) ^ (row & 7)) * 16);
                ldmx4(af[mi][0], af[mi][1], af[mi][2], af[mi][3], addr);
            }
            uint32_t bf[8][2];
            #pragma unroll
            for (int nt = 0; nt < 4; nt++) {
                int row = b_row + nt * 16;
                uint32_t addr = sB + row * 128
                              + (((kk * 2 + b_hi) ^ (row & 7)) * 16);
                uint32_t r0, r1, r2, r3;
                ldmx4(r0, r1, r2, r3, addr);
                bf[nt * 2][0]     = r0; bf[nt * 2][1]     = r1;
                bf[nt * 2 + 1][0] = r2; bf[nt * 2 + 1][1] = r3;
            }
            #pragma unroll
            for (int mi = 0; mi < 2; mi++)
                #pragma unroll
                for (int ni = 0; ni < 8; ni++)
                    mma_fp16(acc[mi][ni], af[mi], bf[ni]);
        }
    }

    // ---------------- fused softmax-partial epilogue -----------------------
    const int quad  = lane >> 2;
    const int cbase = n0 + wn * 64 + (lane & 3) * 2;
    const int tile  = blockIdx.x * 2 + wn;
    const int mode  = g_labmode;

    #pragma unroll
    for (int mi = 0; mi < 2; mi++) {
        #pragma unroll
        for (int off = 0; off < 2; off++) {
            const int row = m0 + wm * 32 + quad + mi * 16 + off * 8;
            const int lab = mode ? l32[row] : l32[2 * row];

            float v[16];
            float mx = -FLT_MAX, ss = 0.f, sl = 0.f;
            #pragma unroll
            for (int ni = 0; ni < 8; ni++) {
                #pragma unroll
                for (int b = 0; b < 2; b++) {
                    const int col = cbase + ni * 8 + b;
                    const float val = 2.f * acc[mi][ni][off * 2 + b];
                    const bool ok = (col < NCLS);
                    v[ni * 2 + b] = ok ? val : -FLT_MAX;
                    if (ok) { mx = fmaxf(mx, val); ss += val; }
                    if (col == lab) sl = val;
                }
            }
            mx = fmaxf(mx, __shfl_xor_sync(0xFFFFFFFFu, mx, 1));
            mx = fmaxf(mx, __shfl_xor_sync(0xFFFFFFFFu, mx, 2));
            float se = 0.f;
            #pragma unroll
            for (int j = 0; j < 16; j++)
                if (v[j] > -FLT_MAX) se += __expf(v[j] - mx);
            se += __shfl_xor_sync(0xFFFFFFFFu, se, 1);
            se += __shfl_xor_sync(0xFFFFFFFFu, se, 2);
            ss += __shfl_xor_sync(0xFFFFFFFFu, ss, 1);
            ss += __shfl_xor_sync(0xFFFFFFFFu, ss, 2);
            sl += __shfl_xor_sync(0xFFFFFFFFu, sl, 1);
            sl += __shfl_xor_sync(0xFFFFFFFFu, sl, 2);

            if ((lane & 3) == 0)
                g_part[tile][row] = make_float4(mx, se, ss, sl);
        }
    }
}

// ---------------------------------------------------------------- combine
// Per-row lse merge + per-block partial sum; last block finishes the mean
// (deterministic: final 64-term sum is in fixed order regardless of which
//  block runs last; g_done self-resets for graph replay).
__global__ void combine_kernel(float* __restrict__ out) {
    __shared__ float warp_sums[8];
    __shared__ int   s_last;
    const int row = blockIdx.x * blockDim.x + threadIdx.x;

    float4 p[NTILES];
    #pragma unroll
    for (int t = 0; t < NTILES; t++) p[t] = g_part[t][row];

    float m = -FLT_MAX;
    #pragma unroll
    for (int t = 0; t < NTILES; t++) m = fmaxf(m, p[t].x);

    float se = 0.f, ss = 0.f, sl = 0.f;
    #pragma unroll
    for (int t = 0; t < NTILES; t++) {
        se += p[t].y * __expf(p[t].x - m);
        ss += p[t].z;
        sl += p[t].w;
    }
    float loss = m + logf(se) - (EPS / (float)NCLS) * ss - (1.0f - EPS) * sl;

    #pragma unroll
    for (int off = 16; off > 0; off >>= 1)
        loss += __shfl_xor_sync(0xFFFFFFFFu, loss, off);
    if ((threadIdx.x & 31) == 0) warp_sums[threadIdx.x >> 5] = loss;
    __syncthreads();
    if (threadIdx.x == 0) {
        float t = 0.f;
        #pragma unroll
        for (int w = 0; w < 8; w++) t += warp_sums[w];
        g_bsum[blockIdx.x] = t;
        __threadfence();
        unsigned prev = atomicAdd(&g_done, 1u);
        s_last = (prev == NBLK - 1);
    }
    __syncthreads();

    if (s_last) {
        float s = (threadIdx.x < NBLK) ? g_bsum[threadIdx.x] : 0.f;
        #pragma unroll
        for (int off = 16; off > 0; off >>= 1)
            s += __shfl_xor_sync(0xFFFFFFFFu, s, off);
        if ((threadIdx.x & 31) == 0) warp_sums[threadIdx.x >> 5] = s;
        __syncthreads();
        if (threadIdx.x == 0) {
            out[0] = (warp_sums[0] + warp_sums[1]) / (float)B_ROWS;
            g_done = 0;                      // reset for next graph replay
        }
    }
}

// ----------------------------------------------------------------------------
extern "C" void kernel_launch(void* const* d_in, const int* in_sizes, int n_in,
                              void* d_out, int out_size) {
    const float* A   = (const float*)d_in[0];   // inputs [16384, 1000]
    const int*   lab = (const int*)d_in[1];     // labels (dtype auto-detected)
    const float* Cb  = (const float*)d_in[2];   // code_book [1000, 1000]
    float* out = (float*)d_out;

    cudaFuncSetAttribute(gemm_kernel,
                         cudaFuncAttributeMaxDynamicSharedMemorySize, SMEM_TOTAL);

    prep_kernel<<<A_BLKS + C_BLKS + 1, 256>>>(A, Cb, lab);
    gemm_kernel<<<dim3(1024 / BN, B_ROWS / BM), 256, SMEM_TOTAL>>>(lab);
    combine_kernel<<<NBLK, 256>>>(out);
}

// round 17
// speedup vs baseline: 1.0404x; 1.0404x over previous
#include <cuda_runtime.h>
#include <cuda_fp16.h>
#include <stdint.h>
#include <math.h>
#include <float.h>

#define B_ROWS 16384
#define NCLS   1000
#define KDIM   1000
#define EPS    0.1f

// GEMM config: centered fp16 single-term, K = 1024
#define KPA     1024
#define BM      128
#define BN      128
#define BK      64            // fp16 K per stage = 128 bytes/row
#define KITERS  (KPA / BK)    // 16
#define NSTAGE  3
#define STAGE_BYTES 32768     // A 16KB + B 16KB
#define SMEM_TOTAL (NSTAGE * STAGE_BYTES)   // 96 KB
#define NTILES  16            // 16 x 64-col softmax partial tiles
#define NBLK    (B_ROWS / 256)              // 64 combine blocks

// Scratch (__device__ globals: allocation-free rule)
__device__ float4   g_part[NTILES][B_ROWS];   // {max, sumexp, sum, S[label]}
__device__ float    g_bsum[NBLK];
__device__ int      g_labmode;
__device__ unsigned g_done;                   // combine last-block counter (self-resetting)
__device__ __half   g_Ah[(size_t)B_ROWS * KPA];  // fp16(a - 0.5)
__device__ __half   g_Ch[(size_t)1024  * KPA];   // fp16(c - 0.5), rows padded

// ---------------------------------------------------------------- PTX helpers
__device__ __forceinline__ uint32_t smem_u32(const void* p) {
    uint32_t a;
    asm("{ .reg .u64 t; cvta.to.shared.u64 t, %1; cvt.u32.u64 %0, t; }" : "=r"(a) : "l"(p));
    return a;
}
#define CP_ASYNC16(dst, src) \
    asm volatile("cp.async.cg.shared.global [%0], [%1], 16;\n" :: "r"(dst), "l"(src))
#define CP_COMMIT() asm volatile("cp.async.commit_group;\n" ::: "memory")
#define CP_WAIT1()  asm volatile("cp.async.wait_group 1;\n" ::: "memory")

// streaming (evict-first) float4 load for read-once data
__device__ __forceinline__ float4 ldg_cs4(const float* p) {
    float4 v;
    asm volatile("ld.global.cs.v4.f32 {%0,%1,%2,%3}, [%4];"
                 : "=f"(v.x), "=f"(v.y), "=f"(v.z), "=f"(v.w) : "l"(p));
    return v;
}

__device__ __forceinline__ void ldmx4(uint32_t& r0, uint32_t& r1, uint32_t& r2,
                                      uint32_t& r3, uint32_t addr) {
    asm volatile("ldmatrix.sync.aligned.m8n8.x4.shared.b16 {%0,%1,%2,%3}, [%4];"
                 : "=r"(r0), "=r"(r1), "=r"(r2), "=r"(r3) : "r"(addr));
}
__device__ __forceinline__ void mma_fp16(float* c, const uint32_t* a, const uint32_t* b) {
    asm volatile("mma.sync.aligned.m16n8k16.row.col.f32.f16.f16.f32 "
                 "{%0,%1,%2,%3}, {%4,%5,%6,%7}, {%8,%9}, {%0,%1,%2,%3};"
                 : "+f"(c[0]), "+f"(c[1]), "+f"(c[2]), "+f"(c[3])
                 : "r"(a[0]), "r"(a[1]), "r"(a[2]), "r"(a[3]), "r"(b[0]), "r"(b[1]));
}

// ------------------------------------------------ fused prep (conv + detect)
// R15-proven 8 elements/thread; fp32 sources read with .cs (read-once).
// blocks [0, 8192)      : convert A
// blocks [8192, 8704)   : convert C
// block  8704           : label-dtype detect + g_done reset
#define A_BLKS 8192
#define C_BLKS 512
__global__ void prep_kernel(const float* __restrict__ A,
                            const float* __restrict__ Cb,
                            const int* __restrict__ l32) {
    const int bid = blockIdx.x;
    if (bid < A_BLKS) {
        size_t t = (size_t)bid * 256 + threadIdx.x;
        int b = (int)(t >> 7);
        int k = (int)(t & 127) << 3;
        float v[8];
        if (k + 8 <= KDIM) {
            float4 x = ldg_cs4(A + (size_t)b * KDIM + k);
            float4 y = ldg_cs4(A + (size_t)b * KDIM + k + 4);
            v[0]=x.x-0.5f; v[1]=x.y-0.5f; v[2]=x.z-0.5f; v[3]=x.w-0.5f;
            v[4]=y.x-0.5f; v[5]=y.y-0.5f; v[6]=y.z-0.5f; v[7]=y.w-0.5f;
        } else {
            #pragma unroll
            for (int i = 0; i < 8; i++) {
                int kk = k + i;
                v[i] = (kk < KDIM) ? (A[(size_t)b * KDIM + kk] - 0.5f) : 0.f;
            }
        }
        union { __half h[8]; uint4 q; } uh;
        #pragma unroll
        for (int i = 0; i < 8; i++) uh.h[i] = __float2half_rn(v[i]);
        *(uint4*)(g_Ah + (size_t)b * KPA + k) = uh.q;
    } else if (bid < A_BLKS + C_BLKS) {
        size_t t = (size_t)(bid - A_BLKS) * 256 + threadIdx.x;
        int n = (int)(t >> 7);
        int k = (int)(t & 127) << 3;
        float v[8];
        if (n < NCLS && k + 8 <= KDIM) {
            float4 x = ldg_cs4(Cb + (size_t)n * KDIM + k);
            float4 y = ldg_cs4(Cb + (size_t)n * KDIM + k + 4);
            v[0]=x.x-0.5f; v[1]=x.y-0.5f; v[2]=x.z-0.5f; v[3]=x.w-0.5f;
            v[4]=y.x-0.5f; v[5]=y.y-0.5f; v[6]=y.z-0.5f; v[7]=y.w-0.5f;
        } else {
            #pragma unroll
            for (int i = 0; i < 8; i++) {
                int kk = k + i;
                v[i] = (n < NCLS && kk < KDIM) ? (Cb[(size_t)n * KDIM + kk] - 0.5f) : 0.f;
            }
        }
        union { __half h[8]; uint4 q; } uh;
        #pragma unroll
        for (int i = 0; i < 8; i++) uh.h[i] = __float2half_rn(v[i]);
        *(uint4*)(g_Ch + (size_t)n * KPA + k) = uh.q;
    } else {
        __shared__ int s_any;
        if (threadIdx.x == 0) { s_any = 0; g_done = 0; }
        __syncthreads();
        int local = 0;
        for (int i = threadIdx.x; i < B_ROWS / 2; i += blockDim.x)
            local |= l32[2 * i + 1];
        if (local) atomicOr(&s_any, 1);
        __syncthreads();
        if (threadIdx.x == 0) g_labmode = (s_any != 0) ? 1 : 0;
    }
}

// ---------------------------------------------------------------- HMMA GEMM
// 8 warps x (32x64) warp tiles on 128x128 CTA tile (R13-proven config).
// Computes S = 2 * (A' @ C'^T) and fused softmax partials per 64-col tile.
__global__ void __launch_bounds__(256, 2)
gemm_kernel(const int* __restrict__ l32) {
    extern __shared__ char smem[];
    const uint32_t sb = smem_u32(smem);

    const int tid  = threadIdx.x;
    const int lane = tid & 31;
    const int wid  = tid >> 5;
    const int wm   = wid >> 1;        // 0..3  -> m offset wm*32
    const int wn   = wid & 1;         // 0..1  -> n offset wn*64
    const int m0   = blockIdx.y * BM;
    const int n0   = blockIdx.x * BN;

    // cp.async staging mapping: each thread owns 4 A-chunks + 4 B-chunks/stage
    const int srow = tid >> 3;        // 0..31 base row
    const int scol = tid & 7;         // chunk 0..7
    const uint32_t sdst = srow * 128 + ((scol ^ (srow & 7)) * 16);
    const __half* Asrc = g_Ah + (size_t)(m0 + srow) * KPA + scol * 8;
    const __half* Bsrc = g_Ch + (size_t)(n0 + srow) * KPA + scol * 8;

    auto load_stage = [&](int s, int st) {
        const int k0 = s * BK;
        const uint32_t sA = sb + st * STAGE_BYTES;
        const uint32_t sB = sA + 16384;
        #pragma unroll
        for (int i = 0; i < 4; i++) {
            uint32_t d = sA + sdst + i * 32 * 128;
            CP_ASYNC16(d, Asrc + (size_t)(32 * i) * KPA + k0);
        }
        #pragma unroll
        for (int i = 0; i < 4; i++) {
            uint32_t d = sB + sdst + i * 32 * 128;
            CP_ASYNC16(d, Bsrc + (size_t)(32 * i) * KPA + k0);
        }
        CP_COMMIT();
    };

    float acc[2][8][4];
    #pragma unroll
    for (int mi = 0; mi < 2; mi++)
        #pragma unroll
        for (int ni = 0; ni < 8; ni++)
            #pragma unroll
            for (int j = 0; j < 4; j++) acc[mi][ni][j] = 0.f;

    const int a_row = wm * 32 + (lane & 15);
    const int a_hi  = lane >> 4;
    const int b_row = wn * 64 + (lane & 7) + ((lane >> 4) << 3);
    const int b_hi  = (lane >> 3) & 1;

    load_stage(0, 0);
    load_stage(1, 1);

    for (int s = 0; s < KITERS; s++) {
        const int st = s % NSTAGE;
        CP_WAIT1();
        __syncthreads();
        if (s + 2 < KITERS) load_stage(s + 2, (s + 2) % NSTAGE);

        const uint32_t sA = sb + st * STAGE_BYTES;
        const uint32_t sB = sA + 16384;

        #pragma unroll
        for (int kk = 0; kk < 4; kk++) {
            uint32_t af[2][4];
            #pragma unroll
            for (int mi = 0; mi < 2; mi++) {
                int row = a_row + mi * 16;
                uint32_t addr = sA + row * 128
                              + (((kk * 2 + a_hi) ^ (row & 7)) * 16);
                ldmx4(af[mi][0], af[mi][1], af[mi][2], af[mi][3], addr);
            }
            uint32_t bf[8][2];
            #pragma unroll
            for (int nt = 0; nt < 4; nt++) {
                int row = b_row + nt * 16;
                uint32_t addr = sB + row * 128
                              + (((kk * 2 + b_hi) ^ (row & 7)) * 16);
                uint32_t r0, r1, r2, r3;
                ldmx4(r0, r1, r2, r3, addr);
                bf[nt * 2][0]     = r0; bf[nt * 2][1]     = r1;
                bf[nt * 2 + 1][0] = r2; bf[nt * 2 + 1][1] = r3;
            }
            #pragma unroll
            for (int mi = 0; mi < 2; mi++)
                #pragma unroll
                for (int ni = 0; ni < 8; ni++)
                    mma_fp16(acc[mi][ni], af[mi], bf[ni]);
        }
    }

    // ---------------- fused softmax-partial epilogue -----------------------
    const int quad  = lane >> 2;
    const int cbase = n0 + wn * 64 + (lane & 3) * 2;
    const int tile  = blockIdx.x * 2 + wn;
    const int mode  = g_labmode;

    #pragma unroll
    for (int mi = 0; mi < 2; mi++) {
        #pragma unroll
        for (int off = 0; off < 2; off++) {
            const int row = m0 + wm * 32 + quad + mi * 16 + off * 8;
            const int lab = mode ? l32[row] : l32[2 * row];

            float v[16];
            float mx = -FLT_MAX, ss = 0.f, sl = 0.f;
            #pragma unroll
            for (int ni = 0; ni < 8; ni++) {
                #pragma unroll
                for (int b = 0; b < 2; b++) {
                    const int col = cbase + ni * 8 + b;
                    const float val = 2.f * acc[mi][ni][off * 2 + b];
                    const bool ok = (col < NCLS);
                    v[ni * 2 + b] = ok ? val : -FLT_MAX;
                    if (ok) { mx = fmaxf(mx, val); ss += val; }
                    if (col == lab) sl = val;
                }
            }
            mx = fmaxf(mx, __shfl_xor_sync(0xFFFFFFFFu, mx, 1));
            mx = fmaxf(mx, __shfl_xor_sync(0xFFFFFFFFu, mx, 2));
            float se = 0.f;
            #pragma unroll
            for (int j = 0; j < 16; j++)
                if (v[j] > -FLT_MAX) se += __expf(v[j] - mx);
            se += __shfl_xor_sync(0xFFFFFFFFu, se, 1);
            se += __shfl_xor_sync(0xFFFFFFFFu, se, 2);
            ss += __shfl_xor_sync(0xFFFFFFFFu, ss, 1);
            ss += __shfl_xor_sync(0xFFFFFFFFu, ss, 2);
            sl += __shfl_xor_sync(0xFFFFFFFFu, sl, 1);
            sl += __shfl_xor_sync(0xFFFFFFFFu, sl, 2);

            if ((lane & 3) == 0)
                g_part[tile][row] = make_float4(mx, se, ss, sl);
        }
    }
}

// ---------------------------------------------------------------- combine
// Per-row lse merge + per-block partial sum; last block finishes the mean
// (deterministic: final 64-term sum is in fixed order regardless of which
//  block runs last; g_done self-resets for graph replay).
__global__ void combine_kernel(float* __restrict__ out) {
    __shared__ float warp_sums[8];
    __shared__ int   s_last;
    const int row = blockIdx.x * blockDim.x + threadIdx.x;

    float4 p[NTILES];
    #pragma unroll
    for (int t = 0; t < NTILES; t++) p[t] = g_part[t][row];

    float m = -FLT_MAX;
    #pragma unroll
    for (int t = 0; t < NTILES; t++) m = fmaxf(m, p[t].x);

    float se = 0.f, ss = 0.f, sl = 0.f;
    #pragma unroll
    for (int t = 0; t < NTILES; t++) {
        se += p[t].y * __expf(p[t].x - m);
        ss += p[t].z;
        sl += p[t].w;
    }
    float loss = m + logf(se) - (EPS / (float)NCLS) * ss - (1.0f - EPS) * sl;

    #pragma unroll
    for (int off = 16; off > 0; off >>= 1)
        loss += __shfl_xor_sync(0xFFFFFFFFu, loss, off);
    if ((threadIdx.x & 31) == 0) warp_sums[threadIdx.x >> 5] = loss;
    __syncthreads();
    if (threadIdx.x == 0) {
        float t = 0.f;
        #pragma unroll
        for (int w = 0; w < 8; w++) t += warp_sums[w];
        g_bsum[blockIdx.x] = t;
        __threadfence();
        unsigned prev = atomicAdd(&g_done, 1u);
        s_last = (prev == NBLK - 1);
    }
    __syncthreads();

    if (s_last) {
        float s = (threadIdx.x < NBLK) ? g_bsum[threadIdx.x] : 0.f;
        #pragma unroll
        for (int off = 16; off > 0; off >>= 1)
            s += __shfl_xor_sync(0xFFFFFFFFu, s, off);
        if ((threadIdx.x & 31) == 0) warp_sums[threadIdx.x >> 5] = s;
        __syncthreads();
        if (threadIdx.x == 0) {
            out[0] = (warp_sums[0] + warp_sums[1]) / (float)B_ROWS;
            g_done = 0;                      // reset for next graph replay
        }
    }
}

// ----------------------------------------------------------------------------
extern "C" void kernel_launch(void* const* d_in, const int* in_sizes, int n_in,
                              void* d_out, int out_size) {
    const float* A   = (const float*)d_in[0];   // inputs [16384, 1000]
    const int*   lab = (const int*)d_in[1];     // labels (dtype auto-detected)
    const float* Cb  = (const float*)d_in[2];   // code_book [1000, 1000]
    float* out = (float*)d_out;

    cudaFuncSetAttribute(gemm_kernel,
                         cudaFuncAttributeMaxDynamicSharedMemorySize, SMEM_TOTAL);

    prep_kernel<<<A_BLKS + C_BLKS + 1, 256>>>(A, Cb, lab);
    gemm_kernel<<<dim3(1024 / BN, B_ROWS / BM), 256, SMEM_TOTAL>>>(lab);
    combine_kernel<<<NBLK, 256>>>(out);
}